// round 3
// baseline (speedup 1.0000x reference)
#include <cuda_runtime.h>

// img: [256, 3, 224, 224] f32, y_idx/x_idx: [256] i32.
// out[b,c,h,w] = img * (0 if h in [y,y+32) && w in [x,x+32) else 1)
//
// HBM-streaming kernel, MLP=8: each thread front-batches 8 coalesced float4
// loads (rows h0 + 4*k, k=0..7, within a 32-row tile), masks, stores.
// __ldcs/__stcs streaming hints — zero reuse.

#define SQ 32
#define BATCH 256
#define CH 3
#define HH 224
#define WW 224
#define W4 (WW / 4)                    // 56 float4 per row
#define TY 4                           // threads in y
#define RPT 8                          // rows per thread
#define TILE_H (TY * RPT)              // 32 rows per block

__global__ __launch_bounds__(W4 * TY)
void random_square_dropout_kernel(const float4* __restrict__ img,
                                  const int* __restrict__ y_idx,
                                  const int* __restrict__ x_idx,
                                  float4* __restrict__ out) {
    const int b  = blockIdx.z;
    const int c  = blockIdx.y;
    const int h0 = blockIdx.x * TILE_H + threadIdx.y;  // rows h0 + TY*k
    const int w4 = threadIdx.x;                        // 0..55

    const int y = __ldg(&y_idx[b]);
    const int x = __ldg(&x_idx[b]);

    const long plane = ((long)b * CH + c) * (long)(HH * W4);
    const long base  = plane + (long)h0 * W4 + w4;

    // Front-batched loads: 8 independent DRAM requests in flight per thread.
    float4 v[RPT];
#pragma unroll
    for (int k = 0; k < RPT; k++)
        v[k] = __ldcs(&img[base + (long)(k * TY) * W4]);

    // Column in-square flags (constant across this thread's rows).
    const int w0 = w4 * 4;
    const bool cx0 = (w0     >= x) && (w0     < x + SQ);
    const bool cx1 = (w0 + 1 >= x) && (w0 + 1 < x + SQ);
    const bool cx2 = (w0 + 2 >= x) && (w0 + 2 < x + SQ);
    const bool cx3 = (w0 + 3 >= x) && (w0 + 3 < x + SQ);

    if (cx0 || cx1 || cx2 || cx3) {
#pragma unroll
        for (int k = 0; k < RPT; k++) {
            const int h = h0 + k * TY;
            if (h >= y && h < y + SQ) {
                if (cx0) v[k].x = 0.f;
                if (cx1) v[k].y = 0.f;
                if (cx2) v[k].z = 0.f;
                if (cx3) v[k].w = 0.f;
            }
        }
    }

#pragma unroll
    for (int k = 0; k < RPT; k++)
        __stcs(&out[base + (long)(k * TY) * W4], v[k]);
}

extern "C" void kernel_launch(void* const* d_in, const int* in_sizes, int n_in,
                              void* d_out, int out_size) {
    const float4* img = (const float4*)d_in[0];
    const int* y_idx  = (const int*)d_in[1];
    const int* x_idx  = (const int*)d_in[2];
    float4* out       = (float4*)d_out;

    dim3 block(W4, TY);                      // 56 x 4 = 224 threads
    dim3 grid(HH / TILE_H, CH, BATCH);       // 7 x 3 x 256 = 5376 blocks
    random_square_dropout_kernel<<<grid, block>>>(img, y_idx, x_idx, out);
}